// round 12
// baseline (speedup 1.0000x reference)
#include <cuda_runtime.h>
#include <cuda_bf16.h>
#include <cstdint>

// Problem constants (fixed by the reference)
#define NT   1024
#define NI   64
#define NO   64
#define NJ   960
#define NA   960
#define WARM 25
#define INVN (1.0f/1024.0f)

typedef unsigned long long u64;
typedef unsigned int u32;

// -------------------- device scratch (no allocations allowed) ----------------
__device__ float g_c0[NJ];        // warm-state constant offset for the batch step
__device__ float g_srt[2][NA];    // sorted enhancer / inhibitor values
__device__ int   g_gxr[2][NA];    // original conc index per sorted slot
__device__ float g_tbl[4][NA];    // exp(+b eS), exp(-b eS), exp(+b iS), exp(-b iS)
__device__ float g_eP[NA];        // exp(+b id_j)
__device__ float g_eM[NA];        // exp(-b id_j)
__device__ __align__(16) uint4 g_Wf[120 * 4 * 32];  // W in mma B-frag layout
// idempotent one-way flags (0 -> 1; deterministic data behind them)
__device__ int g_fsort[14];
__device__ int g_fw[4];
__device__ int g_fc0;

// -------------------- helpers ------------------------------------------------
__device__ __forceinline__ u32 smem_u32(const void* p) {
    u32 a;
    asm("{ .reg .u64 t; cvta.to.shared.u64 t, %1; cvt.u32.u64 %0, t; }"
        : "=r"(a) : "l"(p));
    return a;
}
__device__ __forceinline__ int ld_acq(const int* p) {
    int v;
    asm volatile("ld.acquire.gpu.b32 %0, [%1];" : "=r"(v) : "l"(p) : "memory");
    return v;
}
__device__ __forceinline__ void st_rel(int* p, int v) {
    asm volatile("st.release.gpu.b32 [%0], %1;" :: "l"(p), "r"(v) : "memory");
}
__device__ __forceinline__ void cpa16(u32 dst, const void* src) {
    asm volatile("cp.async.cg.shared.global [%0], [%1], 16;" :: "r"(dst), "l"(src));
}
__device__ __forceinline__ void ldmx4(u32* r, u32 addr) {
    asm volatile("ldmatrix.sync.aligned.m8n8.x4.shared.b16 {%0,%1,%2,%3}, [%4];"
        : "=r"(r[0]), "=r"(r[1]), "=r"(r[2]), "=r"(r[3]) : "r"(addr));
}
__device__ __forceinline__ void mma_bf16(float& d0, float& d1, float& d2, float& d3,
                                         const u32* a, u32 b0, u32 b1) {
    asm volatile("mma.sync.aligned.m16n8k16.row.col.f32.bf16.bf16.f32 "
        "{%0,%1,%2,%3}, {%4,%5,%6,%7}, {%8,%9}, {%0,%1,%2,%3};"
        : "+f"(d0), "+f"(d1), "+f"(d2), "+f"(d3)
        : "r"(a[0]), "r"(a[1]), "r"(a[2]), "r"(a[3]), "r"(b0), "r"(b1));
}
#define SWZ(o) ((o) ^ (((o) >> 3) & 0x70))
#define NB256() asm volatile("bar.sync 1, 256;" ::: "memory")

__device__ __forceinline__ void split2(float a, float b, u32& h, u32& l) {
    __nv_bfloat16 ha = __float2bfloat16(a), hb = __float2bfloat16(b);
    __nv_bfloat16 la = __float2bfloat16(a - __bfloat162float(ha));
    __nv_bfloat16 lb = __float2bfloat16(b - __bfloat162float(hb));
    __nv_bfloat162 hh = __halves2bfloat162(ha, hb);
    __nv_bfloat162 ll = __halves2bfloat162(la, lb);
    h = *(u32*)&hh;  l = *(u32*)&ll;
}

// batch smem layout (dynamic)
#define CH    24
#define CHB   (CH * 4 * 32 * 16)     // 49152 bytes per chunk
#define OF_AHI 0
#define OF_ALO 16384
#define OF_B   32768                 // 2 * CHB = 98304
#define OF_TS  131072                // 128*64*4 = 32768
#define OF_C0  163840                // 960*4 = 3840
#define OF_SUM 167680                // 4*128*4 = 2048
#define OF_SINV 169728               // 128*4
#define SMB    170240

// =============================================================================
__global__ __launch_bounds__(512) void k_mega(const float* __restrict__ in,
                                              const float* __restrict__ ident,
                                              const float* __restrict__ enh,
                                              const float* __restrict__ inh,
                                              const float* __restrict__ beta,
                                              const float* __restrict__ delta,
                                              float* __restrict__ out) {
    extern __shared__ __align__(16) char smb[];
    int bid = blockIdx.x;
    int tid = threadIdx.x, lane = tid & 31, wid = tid >> 5;

    // ===================== sort blocks (133..146) ============================
    if (bid >= 133) {
        int q = bid - 133;
        float b = beta[0];
        float* sv = (float*)smb;                      // [2][960]
        for (int t = tid; t < 2 * NA; t += 512) {
            int m = (t >= NA) ? 1 : 0;
            int e = t - m * NA;
            int k = (e < NI) ? e : e + NO;
            sv[m * NA + e] = (m ? inh : enh)[k];
        }
        __syncthreads();
        int jp = tid & 15;
        #pragma unroll 1
        for (int p = 0; p < 5; ++p) {
            int loc = p * 32 + (tid >> 4);
            int t = q * 138 + loc;
            if (loc < 138 && t < 2 * NA) {
                int m = (t >= NA) ? 1 : 0;
                int e = t - m * NA;
                float v = sv[m * NA + e];
                const float* base = sv + m * NA;
                int rank = 0;
                int j0 = jp * 60;
                #pragma unroll 4
                for (int jj = 0; jj < 60; ++jj) {
                    int j = j0 + jj;
                    float o = base[j];
                    rank += (o < v) || (o == v && j < e);
                }
                #pragma unroll
                for (int off = 1; off < 16; off <<= 1)
                    rank += __shfl_xor_sync(0xffffffffu, rank, off);
                if (jp == 0) {
                    g_srt[m][rank] = v;
                    g_gxr[m][rank] = (e < NI) ? e : e + NO;
                    g_tbl[m * 2][rank]     = expf(b * v);
                    g_tbl[m * 2 + 1][rank] = expf(-b * v);
                }
            }
        }
        __threadfence();
        __syncthreads();
        if (tid == 0) st_rel(&g_fsort[q], 1);
        return;
    }

    // ===================== weight-fill blocks (129..132) =====================
    if (bid >= 129) {
        int r = bid - 129;
        float b = beta[0], dsc = delta[0] * INVN;
        float* ke  = (float*)smb;           // [4][64]: eIp,eIm,hIp,hIm
        float* je  = ke + 256;              // [2][240]: jp, jm
        float* idv = je + 480;              // [240]
        float* ev  = idv + 240;             // [64]
        float* iv  = ev + 64;               // [64]
        if (tid < 64) {
            float e = enh[tid];
            ev[tid] = e;
            ke[tid] = expf(b * e); ke[64 + tid] = expf(-b * e);
        } else if (tid < 128) {
            int k = tid - 64;
            float v = inh[k];
            iv[k] = v;
            ke[128 + k] = expf(b * v); ke[192 + k] = expf(-b * v);
        }
        for (int jj = tid; jj < 240; jj += 512) {
            int j = r * 240 + jj;
            float id = ident[NI + j];
            idv[jj] = id;
            float p = expf(b * id), m = expf(-b * id);
            je[jj] = p; je[240 + jj] = m;
            g_eP[j] = p; g_eM[j] = m;
        }
        __syncthreads();

        for (int i = tid; i < 3840; i += 512) {
            int lt = i >> 7;                 // local tile 0..29
            int rem = i & 127;
            int s = rem >> 5, ln = rem & 31;
            int jl = lt * 8 + (ln >> 2);     // 0..239
            int k0 = s * 16 + (ln & 3) * 2;
            float jpv = je[jl], jmv = je[240 + jl], id = idv[jl];
            float wv[4];
            int ks[4] = {k0, k0 + 1, k0 + 8, k0 + 9};
            #pragma unroll
            for (int u = 0; u < 4; ++u) {
                int k = ks[u];
                float we = (ev[k] >= id) ? ke[64 + k] * jpv : ke[k] * jmv;
                float wi = (iv[k] >= id) ? ke[192 + k] * jpv : ke[128 + k] * jmv;
                wv[u] = (we - wi) * dsc;
            }
            uint4 o;
            split2(wv[0], wv[1], o.x, o.z);
            split2(wv[2], wv[3], o.y, o.w);
            int t = r * 30 + lt;
            g_Wf[t * 128 + s * 32 + ln] = o;
        }
        __threadfence();
        __syncthreads();
        if (tid == 0) st_rel(&g_fw[r], 1);
        return;
    }

    // ===================== warm block (128) ==================================
    if (bid == 128) {
        float* tbl  = (float*)smb;            // 4*960
        float* P    = tbl + 4 * NA;           // 4*960
        float* Pf   = P + 4 * NA;             // 4*960 (first 2*960 = srt temp)
        float* conc = Pf + 4 * NA;            // 1024
        short* gxs  = (short*)(conc + NT);    // 2*960 shorts
        float* toth = (float*)(gxs + 2 * NA); // 8
        float* tothf = toth + 8;              // 8
        float* red  = tothf + 8;              // 8

        if (tid < 14) { while (ld_acq(&g_fsort[tid]) == 0) {} }
        else if (tid < 18) { while (ld_acq(&g_fw[tid - 14]) == 0) {} }
        __syncthreads();

        float dsc = delta[0] * INVN;
        for (int i = tid; i < NA; i += 512) {
            tbl[i]          = g_tbl[0][i];
            tbl[NA + i]     = g_tbl[1][i];
            tbl[2 * NA + i] = g_tbl[2][i];
            tbl[3 * NA + i] = g_tbl[3][i];
            gxs[i]      = (short)g_gxr[0][i];
            gxs[NA + i] = (short)g_gxr[1][i];
            Pf[i]      = g_srt[0][i];         // srt temp
            Pf[NA + i] = g_srt[1][i];
        }
        for (int i = tid; i < NT; i += 512) conc[i] = (i < NI) ? 0.f : INVN;
        __syncthreads();

        int st = wid >> 1, half = wid & 1, ms = st >> 1;
        int e0 = half * 480 + lane * 15;
        float tblr[15]; int gxr[15];
        int pA4[4], pB4[4]; float epj[4], emj[4], efx[4];
        if (tid < 256) {
            #pragma unroll
            for (int i = 0; i < 15; ++i) {
                tblr[i] = tbl[st * NA + e0 + i];
                gxr[i]  = gxs[ms * NA + e0 + i];
            }
            #pragma unroll
            for (int ii = 0; ii < 4; ++ii) {
                int j = tid + ii * 256;
                if (j < NA) {
                    epj[ii] = g_eP[j];
                    emj[ii] = g_eM[j];
                    float id = ident[NI + j];
                    int lo = 0, hi = NA;
                    while (lo < hi) { int mid = (lo + hi) >> 1; if (Pf[mid] <= id) lo = mid + 1; else hi = mid; }
                    pA4[ii] = lo;
                    lo = 0; hi = NA;
                    while (lo < hi) { int mid = (lo + hi) >> 1; if (Pf[NA + mid] <= id) lo = mid + 1; else hi = mid; }
                    pB4[ii] = lo;
                } else {
                    epj[ii] = 0.f; emj[ii] = 0.f;
                    pA4[ii] = 0; pB4[ii] = 0;
                }
            }
        }
        __syncthreads();     // searches done before Pf overwritten

        // ---- fixed-part (k<NI) prefix scans, computed once ----
        if (tid < 256) {
            float loc[15];
            float runA = 0.f, runB = 0.f;
            #pragma unroll
            for (int i = 0; i < 8; ++i) {
                float cv = (gxr[i] < NI) ? tblr[i] : 0.f;
                runA += cv; loc[i] = runA;
            }
            #pragma unroll
            for (int i = 8; i < 15; ++i) {
                float cv = (gxr[i] < NI) ? tblr[i] : 0.f;
                runB += cv; loc[i] = runB;
            }
            float run = runA + runB;
            float v = run;
            #pragma unroll
            for (int off = 1; off < 32; off <<= 1) {
                float t = __shfl_up_sync(0xffffffffu, v, off);
                if (lane >= off) v += t;
            }
            float excl = v - run;
            #pragma unroll
            for (int i = 0; i < 8; ++i)  Pf[st * NA + e0 + i] = loc[i] + excl;
            float exclB = excl + runA;
            #pragma unroll
            for (int i = 8; i < 15; ++i) Pf[st * NA + e0 + i] = loc[i] + exclB;
            if (lane == 31) tothf[st * 2 + half] = v;
        }
        __syncthreads();

        if (tid < 256) {
            float TF1 = tothf[2] + tothf[3];
            float TF3 = tothf[6] + tothf[7];
            #pragma unroll
            for (int ii = 0; ii < 4; ++ii) {
                efx[ii] = 0.f;
                int j = tid + ii * 256;
                if (j < NA) {
                    int pA = pA4[ii], pB = pB4[ii];
                    float PfA0 = 0.f, PfA1 = 0.f, PfB2 = 0.f, PfB3 = 0.f;
                    if (pA) {
                        int ix = pA - 1;
                        float o = (ix >= 480) ? 1.f : 0.f;
                        PfA0 = Pf[ix] + o * tothf[0];
                        PfA1 = Pf[NA + ix] + o * tothf[2];
                    }
                    if (pB) {
                        int ix = pB - 1;
                        float o = (ix >= 480) ? 1.f : 0.f;
                        PfB2 = Pf[2 * NA + ix] + o * tothf[4];
                        PfB3 = Pf[3 * NA + ix] + o * tothf[6];
                    }
                    float Ef = emj[ii] * PfA0 + epj[ii] * (TF1 - PfA1)
                             - emj[ii] * PfB2 - epj[ii] * (TF3 - PfB3);
                    efx[ii] = dsc * INVN * Ef;
                }
            }
        }
        __syncthreads();
        if (tid >= 256) return;

        float lsum = (tid == 0) ? 1.f : 0.f;    // seeds s_0 = 1
        float nv[4];

        for (int it = 0; it <= WARM; ++it) {
            bool cp = (it == WARM);
            // ---- reduce previous lsum (interleaves with gather chain) ----
            float ls = lsum;
            #pragma unroll
            for (int off = 16; off > 0; off >>= 1)
                ls += __shfl_xor_sync(0xffffffffu, ls, off);
            if (lane == 0) red[wid] = ls;

            // ---- phase 1: unconditional gather + dual-chain scan ----
            float loc[15];
            float runA = 0.f, runB = 0.f;
            #pragma unroll
            for (int i = 0; i < 8; ++i) {
                runA += conc[gxr[i]] * tblr[i];
                loc[i] = runA;
            }
            #pragma unroll
            for (int i = 8; i < 15; ++i) {
                runB += conc[gxr[i]] * tblr[i];
                loc[i] = runB;
            }
            float run = runA + runB;
            float v = run;
            #pragma unroll
            for (int off = 1; off < 32; off <<= 1) {
                float t = __shfl_up_sync(0xffffffffu, v, off);
                if (lane >= off) v += t;
            }
            float excl = v - run;
            #pragma unroll
            for (int i = 0; i < 8; ++i)  P[st * NA + e0 + i] = loc[i] + excl;
            float exclB = excl + runA;
            #pragma unroll
            for (int i = 8; i < 15; ++i) P[st * NA + e0 + i] = loc[i] + exclB;
            if (lane == 31) toth[st * 2 + half] = v;
            NB256();

            // ---- phase 2 ----
            float s = ((red[0] + red[1]) + (red[2] + red[3]))
                    + ((red[4] + red[5]) + (red[6] + red[7]));
            float inv = (s > 0.f) ? 1.f / s : 1.f;
            float t1 = toth[2] + toth[3];
            float t3 = toth[6] + toth[7];
            lsum = 0.f;
            #pragma unroll
            for (int ii = 0; ii < 4; ++ii) {
                int j = tid + ii * 256;
                nv[ii] = 0.f;
                if (j < NA) {
                    int pA = pA4[ii], pB = pB4[ii];
                    float preA0 = 0.f, preA1 = 0.f, preB2 = 0.f, preB3 = 0.f;
                    if (pA) {
                        int ix = pA - 1;
                        float o = (ix >= 480) ? 1.f : 0.f;
                        preA0 = P[ix] + o * toth[0];
                        preA1 = P[NA + ix] + o * toth[2];
                    }
                    if (pB) {
                        int ix = pB - 1;
                        float o = (ix >= 480) ? 1.f : 0.f;
                        preB2 = P[2 * NA + ix] + o * toth[4];
                        preB3 = P[3 * NA + ix] + o * toth[6];
                    }
                    float E = emj[ii] * preA0 + epj[ii] * (t1 - preA1);
                    float I = emj[ii] * preB2 + epj[ii] * (t3 - preB3);
                    float cur = conc[NI + j] * inv;
                    if (cp) {
                        g_c0[j] = cur + dsc * inv * (E - I);
                    } else {
                        float val = cur + dsc * inv * (E - I) + efx[ii];
                        nv[ii] = fmaxf(val, 0.f);
                        lsum += nv[ii];
                    }
                }
            }
            if (cp) break;
            #pragma unroll
            for (int ii = 0; ii < 4; ++ii) {
                int j = tid + ii * 256;
                if (j < NA) conc[NI + j] = nv[ii];    // unnormalized
            }
            NB256();
        }
        __threadfence();
        NB256();
        if (tid == 0) st_rel(&g_fc0, 1);
        return;
    }

    // ===================== batch blocks (0..127) =============================
    u32 sb = smem_u32(smb);
    float* Ts   = (float*)(smb + OF_TS);
    float* c0s  = (float*)(smb + OF_C0);
    float* sums = (float*)(smb + OF_SUM);
    float* sinv = (float*)(smb + OF_SINV);
    int warpM = wid >> 2, warpN = wid & 3;
    int m0 = bid * 128;

    // wait for W (fast now), then prefetch chunks 0 AND 1
    if (tid < 4) { while (ld_acq(&g_fw[tid]) == 0) {} }
    __syncthreads();
    for (int i = tid; i < CHB / 16; i += 512)
        cpa16(sb + OF_B + i * 16, (const char*)g_Wf + i * 16);
    asm volatile("cp.async.commit_group;" ::: "memory");
    for (int i = tid; i < CHB / 16; i += 512)
        cpa16(sb + OF_B + CHB + i * 16, (const char*)g_Wf + CHB + i * 16);
    asm volatile("cp.async.commit_group;" ::: "memory");

    // stage A as swizzled bf16 hi/lo
    for (int idx = tid; idx < 128 * 8; idx += 512) {
        int m = idx >> 3, c = idx & 7;
        const float4* p = (const float4*)(in + (size_t)(m0 + m) * 64 + c * 8);
        float4 v0 = p[0], v1 = p[1];
        uint4 H, L;
        split2(v0.x, v0.y, H.x, L.x); split2(v0.z, v0.w, H.y, L.y);
        split2(v1.x, v1.y, H.z, L.z); split2(v1.z, v1.w, H.w, L.w);
        u32 off = SWZ(m * 128 + c * 16);
        *(uint4*)(smb + OF_AHI + off) = H;
        *(uint4*)(smb + OF_ALO + off) = L;
    }
    __syncthreads();

    // A fragments (held in registers for the whole kernel)
    u32 ah[2][4][4], al[2][4][4];
    {
        int sub = lane >> 3;
        int rr = (lane & 7) + (sub & 1) * 8;
        int kb = (sub >> 1) * 16;
        #pragma unroll
        for (int mt = 0; mt < 2; ++mt)
            #pragma unroll
            for (int s = 0; s < 4; ++s) {
                u32 off = SWZ((warpM * 32 + mt * 16 + rr) * 128 + s * 32 + kb);
                ldmx4(ah[mt][s], sb + OF_AHI + off);
                ldmx4(al[mt][s], sb + OF_ALO + off);
            }
    }

    // wait for c0, stage it
    if (tid == 0) { while (ld_acq(&g_fc0) == 0) {} }
    __syncthreads();
    for (int i = tid; i < NJ; i += 512) c0s[i] = g_c0[i];
    __syncthreads();

    float rs[2][2] = {{0.f, 0.f}, {0.f, 0.f}};

    for (int c = 0; c < 5; ++c) {
        if (c) __syncthreads();
        if (c >= 1 && c < 4) {
            const char* src = (const char*)g_Wf + (size_t)(c + 1) * CHB;
            u32 dstb = sb + OF_B + ((c + 1) & 1) * CHB;
            for (int i = tid; i < CHB / 16; i += 512)
                cpa16(dstb + i * 16, src + i * 16);
            asm volatile("cp.async.commit_group;" ::: "memory");
        }
        if (c < 4) {
            asm volatile("cp.async.wait_group 1;" ::: "memory");
        } else {
            asm volatile("cp.async.wait_group 0;" ::: "memory");
        }
        __syncthreads();

        const uint4* Bp = (const uint4*)(smb + OF_B + (c & 1) * CHB);
        #pragma unroll 1
        for (int nt = 0; nt < 6; ++nt) {
            int lt = warpN * 6 + nt;
            int tG = c * CH + lt;
            uint4 bf[4];
            #pragma unroll
            for (int s = 0; s < 4; ++s)
                bf[s] = Bp[(lt * 4 + s) * 32 + lane];

            int colb = tG * 8 + (lane & 3) * 2;
            float c00 = c0s[colb], c01 = c0s[colb + 1];

            #pragma unroll
            for (int mt = 0; mt < 2; ++mt) {
                float h0 = 0.f, h1 = 0.f, h2 = 0.f, h3 = 0.f;     // hi*hi
                float l0 = 0.f, l1 = 0.f, l2 = 0.f, l3 = 0.f;     // lo*hi
                float m0f = 0.f, m1f = 0.f, m2f = 0.f, m3f = 0.f; // hi*lo
                #pragma unroll
                for (int s = 0; s < 4; ++s) {
                    mma_bf16(h0, h1, h2, h3, ah[mt][s], bf[s].x, bf[s].y);
                    mma_bf16(l0, l1, l2, l3, al[mt][s], bf[s].x, bf[s].y);
                    mma_bf16(m0f, m1f, m2f, m3f, ah[mt][s], bf[s].z, bf[s].w);
                }
                float d0 = (h0 + l0) + m0f, d1 = (h1 + l1) + m1f;
                float d2 = (h2 + l2) + m2f, d3 = (h3 + l3) + m3f;
                float t0 = fmaxf(d0 + c00, 0.f), t1 = fmaxf(d1 + c01, 0.f);
                float t2 = fmaxf(d2 + c00, 0.f), t3 = fmaxf(d3 + c01, 0.f);
                rs[mt][0] += t0 + t1;
                rs[mt][1] += t2 + t3;
                if (tG < 8) {
                    int r0 = warpM * 32 + mt * 16 + (lane >> 2);
                    float2 p0 = {t0, t1}, p1 = {t2, t3};
                    *(float2*)&Ts[r0 * 64 + colb] = p0;
                    *(float2*)&Ts[(r0 + 8) * 64 + colb] = p1;
                }
            }
        }
    }

    // rowsums: reduce over the 4 col-lanes of each quad
    #pragma unroll
    for (int mt = 0; mt < 2; ++mt)
        #pragma unroll
        for (int h = 0; h < 2; ++h) {
            rs[mt][h] += __shfl_xor_sync(0xffffffffu, rs[mt][h], 1);
            rs[mt][h] += __shfl_xor_sync(0xffffffffu, rs[mt][h], 2);
        }
    if ((lane & 3) == 0) {
        int rq = lane >> 2;
        #pragma unroll
        for (int mt = 0; mt < 2; ++mt) {
            sums[warpN * 128 + warpM * 32 + mt * 16 + rq] = rs[mt][0];
            sums[warpN * 128 + warpM * 32 + mt * 16 + 8 + rq] = rs[mt][1];
        }
    }
    __syncthreads();
    if (tid < 128) {
        float s = (sums[tid] + sums[128 + tid]) + (sums[256 + tid] + sums[384 + tid]);
        sinv[tid] = (s > 0.f) ? 1.f / s : 1.f;
    }
    __syncthreads();

    for (int idx = tid; idx < 128 * 32; idx += 512) {
        int r = idx >> 5, h2 = idx & 31;
        float2 t = *(float2*)&Ts[r * 64 + h2 * 2];
        float iv = sinv[r];
        float2 o; o.x = t.x * iv; o.y = t.y * iv;
        *(float2*)(out + (size_t)(m0 + r) * 64 + h2 * 2) = o;
    }
}

// -------------------- launch -------------------------------------------------
extern "C" void kernel_launch(void* const* d_in, const int* in_sizes, int n_in,
                              void* d_out, int out_size) {
    const float* inputs = (const float*)d_in[0];
    const float* ident  = (const float*)d_in[1];
    const float* enh    = (const float*)d_in[2];
    const float* inh    = (const float*)d_in[3];
    const float* beta   = (const float*)d_in[4];
    const float* delta  = (const float*)d_in[5];
    float* out = (float*)d_out;

    static int smset = 0;
    if (!smset) {
        cudaFuncSetAttribute(k_mega, cudaFuncAttributeMaxDynamicSharedMemorySize, SMB);
        smset = 1;
    }

    k_mega<<<147, 512, SMB>>>(inputs, ident, enh, inh, beta, delta, out);
}

// round 13
// speedup vs baseline: 1.2221x; 1.2221x over previous
#include <cuda_runtime.h>
#include <cuda_bf16.h>
#include <cstdint>

// Problem constants (fixed by the reference)
#define NT   1024
#define NI   64
#define NO   64
#define NJ   960
#define NA   960
#define WARM 25
#define INVN (1.0f/1024.0f)

typedef unsigned long long u64;
typedef unsigned int u32;

// -------------------- device scratch (no allocations allowed) ----------------
__device__ float g_c0[NJ];        // warm-state constant offset for the batch step
__device__ float g_srt[2][NA];    // sorted enhancer / inhibitor values
__device__ int   g_gxr[2][NA];    // original conc index per sorted slot
__device__ float g_tbl[4][NA];    // exp(+b eS), exp(-b eS), exp(+b iS), exp(-b iS)
__device__ float g_eP[NA];        // exp(+b id_j)
__device__ float g_eM[NA];        // exp(-b id_j)
__device__ __align__(16) uint4 g_Wf[120 * 4 * 32];  // W in mma B-frag layout
__device__ __align__(16) float g_G[128 * 128 * NJ]; // raw GEMM scratch (L2-resident)
// idempotent one-way flags (0 -> 1; deterministic data behind them)
__device__ int g_fsort[14];
__device__ int g_fw[4];
__device__ int g_fc0;

// -------------------- helpers ------------------------------------------------
__device__ __forceinline__ u32 smem_u32(const void* p) {
    u32 a;
    asm("{ .reg .u64 t; cvta.to.shared.u64 t, %1; cvt.u32.u64 %0, t; }"
        : "=r"(a) : "l"(p));
    return a;
}
__device__ __forceinline__ int ld_acq(const int* p) {
    int v;
    asm volatile("ld.acquire.gpu.b32 %0, [%1];" : "=r"(v) : "l"(p) : "memory");
    return v;
}
__device__ __forceinline__ void st_rel(int* p, int v) {
    asm volatile("st.release.gpu.b32 [%0], %1;" :: "l"(p), "r"(v) : "memory");
}
__device__ __forceinline__ void cpa16(u32 dst, const void* src) {
    asm volatile("cp.async.cg.shared.global [%0], [%1], 16;" :: "r"(dst), "l"(src));
}
__device__ __forceinline__ void ldmx4(u32* r, u32 addr) {
    asm volatile("ldmatrix.sync.aligned.m8n8.x4.shared.b16 {%0,%1,%2,%3}, [%4];"
        : "=r"(r[0]), "=r"(r[1]), "=r"(r[2]), "=r"(r[3]) : "r"(addr));
}
__device__ __forceinline__ void mma_bf16(float& d0, float& d1, float& d2, float& d3,
                                         const u32* a, u32 b0, u32 b1) {
    asm volatile("mma.sync.aligned.m16n8k16.row.col.f32.bf16.bf16.f32 "
        "{%0,%1,%2,%3}, {%4,%5,%6,%7}, {%8,%9}, {%0,%1,%2,%3};"
        : "+f"(d0), "+f"(d1), "+f"(d2), "+f"(d3)
        : "r"(a[0]), "r"(a[1]), "r"(a[2]), "r"(a[3]), "r"(b0), "r"(b1));
}
#define SWZ(o) ((o) ^ (((o) >> 3) & 0x70))
#define NB256() asm volatile("bar.sync 1, 256;" ::: "memory")

__device__ __forceinline__ void split2(float a, float b, u32& h, u32& l) {
    __nv_bfloat16 ha = __float2bfloat16(a), hb = __float2bfloat16(b);
    __nv_bfloat16 la = __float2bfloat16(a - __bfloat162float(ha));
    __nv_bfloat16 lb = __float2bfloat16(b - __bfloat162float(hb));
    __nv_bfloat162 hh = __halves2bfloat162(ha, hb);
    __nv_bfloat162 ll = __halves2bfloat162(la, lb);
    h = *(u32*)&hh;  l = *(u32*)&ll;
}

// batch smem layout (dynamic)
#define CH    24
#define CHB   (CH * 4 * 32 * 16)     // 49152 bytes per chunk
#define OF_AHI 0
#define OF_ALO 16384
#define OF_B   32768                 // 2 * CHB = 98304
#define OF_C0  131072                // 960*4 = 3840
#define SMB    135168

// =============================================================================
__global__ __launch_bounds__(512) void k_mega(const float* __restrict__ in,
                                              const float* __restrict__ ident,
                                              const float* __restrict__ enh,
                                              const float* __restrict__ inh,
                                              const float* __restrict__ beta,
                                              const float* __restrict__ delta,
                                              float* __restrict__ out) {
    extern __shared__ __align__(16) char smb[];
    int bid = blockIdx.x;
    int tid = threadIdx.x, lane = tid & 31, wid = tid >> 5;

    // ===================== sort blocks (133..146) ============================
    if (bid >= 133) {
        int q = bid - 133;
        float b = beta[0];
        float* sv = (float*)smb;                      // [2][960]
        for (int t = tid; t < 2 * NA; t += 512) {
            int m = (t >= NA) ? 1 : 0;
            int e = t - m * NA;
            int k = (e < NI) ? e : e + NO;
            sv[m * NA + e] = (m ? inh : enh)[k];
        }
        __syncthreads();
        int jp = tid & 15;
        #pragma unroll 1
        for (int p = 0; p < 5; ++p) {
            int loc = p * 32 + (tid >> 4);
            int t = q * 138 + loc;
            if (loc < 138 && t < 2 * NA) {
                int m = (t >= NA) ? 1 : 0;
                int e = t - m * NA;
                float v = sv[m * NA + e];
                const float* base = sv + m * NA;
                int rank = 0;
                int j0 = jp * 60;
                #pragma unroll 4
                for (int jj = 0; jj < 60; ++jj) {
                    int j = j0 + jj;
                    float o = base[j];
                    rank += (o < v) || (o == v && j < e);
                }
                #pragma unroll
                for (int off = 1; off < 16; off <<= 1)
                    rank += __shfl_xor_sync(0xffffffffu, rank, off);
                if (jp == 0) {
                    g_srt[m][rank] = v;
                    g_gxr[m][rank] = (e < NI) ? e : e + NO;
                    g_tbl[m * 2][rank]     = expf(b * v);
                    g_tbl[m * 2 + 1][rank] = expf(-b * v);
                }
            }
        }
        __threadfence();
        __syncthreads();
        if (tid == 0) st_rel(&g_fsort[q], 1);
        return;
    }

    // ===================== weight-fill blocks (129..132) =====================
    if (bid >= 129) {
        int r = bid - 129;
        float b = beta[0], dsc = delta[0] * INVN;
        float* ke  = (float*)smb;           // [4][64]: eIp,eIm,hIp,hIm
        float* je  = ke + 256;              // [2][240]: jp, jm
        float* idv = je + 480;              // [240]
        float* ev  = idv + 240;             // [64]
        float* iv  = ev + 64;               // [64]
        if (tid < 64) {
            float e = enh[tid];
            ev[tid] = e;
            ke[tid] = expf(b * e); ke[64 + tid] = expf(-b * e);
        } else if (tid < 128) {
            int k = tid - 64;
            float v = inh[k];
            iv[k] = v;
            ke[128 + k] = expf(b * v); ke[192 + k] = expf(-b * v);
        }
        for (int jj = tid; jj < 240; jj += 512) {
            int j = r * 240 + jj;
            float id = ident[NI + j];
            idv[jj] = id;
            float p = expf(b * id), m = expf(-b * id);
            je[jj] = p; je[240 + jj] = m;
            g_eP[j] = p; g_eM[j] = m;
        }
        __syncthreads();

        for (int i = tid; i < 3840; i += 512) {
            int lt = i >> 7;                 // local tile 0..29
            int rem = i & 127;
            int s = rem >> 5, ln = rem & 31;
            int jl = lt * 8 + (ln >> 2);     // 0..239
            int k0 = s * 16 + (ln & 3) * 2;
            float jpv = je[jl], jmv = je[240 + jl], id = idv[jl];
            float wv[4];
            int ks[4] = {k0, k0 + 1, k0 + 8, k0 + 9};
            #pragma unroll
            for (int u = 0; u < 4; ++u) {
                int k = ks[u];
                float we = (ev[k] >= id) ? ke[64 + k] * jpv : ke[k] * jmv;
                float wi = (iv[k] >= id) ? ke[192 + k] * jpv : ke[128 + k] * jmv;
                wv[u] = (we - wi) * dsc;
            }
            uint4 o;
            split2(wv[0], wv[1], o.x, o.z);
            split2(wv[2], wv[3], o.y, o.w);
            int t = r * 30 + lt;
            g_Wf[t * 128 + s * 32 + ln] = o;
        }
        __threadfence();
        __syncthreads();
        if (tid == 0) st_rel(&g_fw[r], 1);
        return;
    }

    // ===================== warm block (128) ==================================
    if (bid == 128) {
        float* tbl  = (float*)smb;            // 4*960
        float* P    = tbl + 4 * NA;           // 4*960
        float* Pf   = P + 4 * NA;             // 4*960 (first 2*960 = srt temp)
        float* conc = Pf + 4 * NA;            // 1024
        short* gxs  = (short*)(conc + NT);    // 2*960 shorts
        float* toth = (float*)(gxs + 2 * NA); // 8
        float* tothf = toth + 8;              // 8
        float* red  = tothf + 8;              // 8

        if (tid < 14) { while (ld_acq(&g_fsort[tid]) == 0) {} }
        else if (tid < 18) { while (ld_acq(&g_fw[tid - 14]) == 0) {} }
        __syncthreads();

        float dsc = delta[0] * INVN;
        for (int i = tid; i < NA; i += 512) {
            tbl[i]          = g_tbl[0][i];
            tbl[NA + i]     = g_tbl[1][i];
            tbl[2 * NA + i] = g_tbl[2][i];
            tbl[3 * NA + i] = g_tbl[3][i];
            gxs[i]      = (short)g_gxr[0][i];
            gxs[NA + i] = (short)g_gxr[1][i];
            Pf[i]      = g_srt[0][i];         // srt temp
            Pf[NA + i] = g_srt[1][i];
        }
        for (int i = tid; i < NT; i += 512) conc[i] = (i < NI) ? 0.f : INVN;
        __syncthreads();

        int st = wid >> 1, half = wid & 1, ms = st >> 1;
        int e0 = half * 480 + lane * 15;
        float tblr[15]; int gxr[15];
        int pA4[4], pB4[4]; float epj[4], emj[4], efx[4];
        if (tid < 256) {
            #pragma unroll
            for (int i = 0; i < 15; ++i) {
                tblr[i] = tbl[st * NA + e0 + i];
                gxr[i]  = gxs[ms * NA + e0 + i];
            }
            #pragma unroll
            for (int ii = 0; ii < 4; ++ii) {
                int j = tid + ii * 256;
                if (j < NA) {
                    epj[ii] = g_eP[j];
                    emj[ii] = g_eM[j];
                    float id = ident[NI + j];
                    int lo = 0, hi = NA;
                    while (lo < hi) { int mid = (lo + hi) >> 1; if (Pf[mid] <= id) lo = mid + 1; else hi = mid; }
                    pA4[ii] = lo;
                    lo = 0; hi = NA;
                    while (lo < hi) { int mid = (lo + hi) >> 1; if (Pf[NA + mid] <= id) lo = mid + 1; else hi = mid; }
                    pB4[ii] = lo;
                } else {
                    epj[ii] = 0.f; emj[ii] = 0.f;
                    pA4[ii] = 0; pB4[ii] = 0;
                }
            }
        }
        __syncthreads();     // searches done before Pf overwritten

        // ---- fixed-part (k<NI) prefix scans, computed once ----
        if (tid < 256) {
            float loc[15];
            float runA = 0.f, runB = 0.f;
            #pragma unroll
            for (int i = 0; i < 8; ++i) {
                float cv = (gxr[i] < NI) ? tblr[i] : 0.f;
                runA += cv; loc[i] = runA;
            }
            #pragma unroll
            for (int i = 8; i < 15; ++i) {
                float cv = (gxr[i] < NI) ? tblr[i] : 0.f;
                runB += cv; loc[i] = runB;
            }
            float run = runA + runB;
            float v = run;
            #pragma unroll
            for (int off = 1; off < 32; off <<= 1) {
                float t = __shfl_up_sync(0xffffffffu, v, off);
                if (lane >= off) v += t;
            }
            float excl = v - run;
            #pragma unroll
            for (int i = 0; i < 8; ++i)  Pf[st * NA + e0 + i] = loc[i] + excl;
            float exclB = excl + runA;
            #pragma unroll
            for (int i = 8; i < 15; ++i) Pf[st * NA + e0 + i] = loc[i] + exclB;
            if (lane == 31) tothf[st * 2 + half] = v;
        }
        __syncthreads();

        if (tid < 256) {
            float TF1 = tothf[2] + tothf[3];
            float TF3 = tothf[6] + tothf[7];
            #pragma unroll
            for (int ii = 0; ii < 4; ++ii) {
                efx[ii] = 0.f;
                int j = tid + ii * 256;
                if (j < NA) {
                    int pA = pA4[ii], pB = pB4[ii];
                    float PfA0 = 0.f, PfA1 = 0.f, PfB2 = 0.f, PfB3 = 0.f;
                    if (pA) {
                        int ix = pA - 1;
                        float o = (ix >= 480) ? 1.f : 0.f;
                        PfA0 = Pf[ix] + o * tothf[0];
                        PfA1 = Pf[NA + ix] + o * tothf[2];
                    }
                    if (pB) {
                        int ix = pB - 1;
                        float o = (ix >= 480) ? 1.f : 0.f;
                        PfB2 = Pf[2 * NA + ix] + o * tothf[4];
                        PfB3 = Pf[3 * NA + ix] + o * tothf[6];
                    }
                    float Ef = emj[ii] * PfA0 + epj[ii] * (TF1 - PfA1)
                             - emj[ii] * PfB2 - epj[ii] * (TF3 - PfB3);
                    efx[ii] = dsc * INVN * Ef;
                }
            }
        }
        __syncthreads();
        if (tid >= 256) return;

        float lsum = (tid == 0) ? 1.f : 0.f;    // seeds s_0 = 1
        float nv[4];

        for (int it = 0; it <= WARM; ++it) {
            bool cp = (it == WARM);
            // ---- reduce previous lsum (interleaves with gather chain) ----
            float ls = lsum;
            #pragma unroll
            for (int off = 16; off > 0; off >>= 1)
                ls += __shfl_xor_sync(0xffffffffu, ls, off);
            if (lane == 0) red[wid] = ls;

            // ---- phase 1: unconditional gather + dual-chain scan ----
            float loc[15];
            float runA = 0.f, runB = 0.f;
            #pragma unroll
            for (int i = 0; i < 8; ++i) {
                runA += conc[gxr[i]] * tblr[i];
                loc[i] = runA;
            }
            #pragma unroll
            for (int i = 8; i < 15; ++i) {
                runB += conc[gxr[i]] * tblr[i];
                loc[i] = runB;
            }
            float run = runA + runB;
            float v = run;
            #pragma unroll
            for (int off = 1; off < 32; off <<= 1) {
                float t = __shfl_up_sync(0xffffffffu, v, off);
                if (lane >= off) v += t;
            }
            float excl = v - run;
            #pragma unroll
            for (int i = 0; i < 8; ++i)  P[st * NA + e0 + i] = loc[i] + excl;
            float exclB = excl + runA;
            #pragma unroll
            for (int i = 8; i < 15; ++i) P[st * NA + e0 + i] = loc[i] + exclB;
            if (lane == 31) toth[st * 2 + half] = v;
            NB256();

            // ---- phase 2 ----
            float s = ((red[0] + red[1]) + (red[2] + red[3]))
                    + ((red[4] + red[5]) + (red[6] + red[7]));
            float inv = (s > 0.f) ? 1.f / s : 1.f;
            float t1 = toth[2] + toth[3];
            float t3 = toth[6] + toth[7];
            lsum = 0.f;
            #pragma unroll
            for (int ii = 0; ii < 4; ++ii) {
                int j = tid + ii * 256;
                nv[ii] = 0.f;
                if (j < NA) {
                    int pA = pA4[ii], pB = pB4[ii];
                    float preA0 = 0.f, preA1 = 0.f, preB2 = 0.f, preB3 = 0.f;
                    if (pA) {
                        int ix = pA - 1;
                        float o = (ix >= 480) ? 1.f : 0.f;
                        preA0 = P[ix] + o * toth[0];
                        preA1 = P[NA + ix] + o * toth[2];
                    }
                    if (pB) {
                        int ix = pB - 1;
                        float o = (ix >= 480) ? 1.f : 0.f;
                        preB2 = P[2 * NA + ix] + o * toth[4];
                        preB3 = P[3 * NA + ix] + o * toth[6];
                    }
                    float E = emj[ii] * preA0 + epj[ii] * (t1 - preA1);
                    float I = emj[ii] * preB2 + epj[ii] * (t3 - preB3);
                    float cur = conc[NI + j] * inv;
                    if (cp) {
                        g_c0[j] = cur + dsc * inv * (E - I);
                    } else {
                        float val = cur + dsc * inv * (E - I) + efx[ii];
                        nv[ii] = fmaxf(val, 0.f);
                        lsum += nv[ii];
                    }
                }
            }
            if (cp) break;
            #pragma unroll
            for (int ii = 0; ii < 4; ++ii) {
                int j = tid + ii * 256;
                if (j < NA) conc[NI + j] = nv[ii];    // unnormalized
            }
            NB256();
        }
        __threadfence();
        NB256();
        if (tid == 0) st_rel(&g_fc0, 1);
        return;
    }

    // ===================== batch blocks (0..127) =============================
    u32 sb = smem_u32(smb);
    float* c0s  = (float*)(smb + OF_C0);
    int warpM = wid >> 2, warpN = wid & 3;
    int m0 = bid * 128;
    float* Gb = g_G + (size_t)bid * (128 * NJ);

    // stage A as swizzled bf16 hi/lo (no dependency on producers)
    for (int idx = tid; idx < 128 * 8; idx += 512) {
        int m = idx >> 3, c = idx & 7;
        const float4* p = (const float4*)(in + (size_t)(m0 + m) * 64 + c * 8);
        float4 v0 = p[0], v1 = p[1];
        uint4 H, L;
        split2(v0.x, v0.y, H.x, L.x); split2(v0.z, v0.w, H.y, L.y);
        split2(v1.x, v1.y, H.z, L.z); split2(v1.z, v1.w, H.w, L.w);
        u32 off = SWZ(m * 128 + c * 16);
        *(uint4*)(smb + OF_AHI + off) = H;
        *(uint4*)(smb + OF_ALO + off) = L;
    }
    // wait for W (ready ~2us), then prefetch chunks 0 AND 1
    if (tid < 4) { while (ld_acq(&g_fw[tid]) == 0) {} }
    __syncthreads();
    for (int i = tid; i < CHB / 16; i += 512)
        cpa16(sb + OF_B + i * 16, (const char*)g_Wf + i * 16);
    asm volatile("cp.async.commit_group;" ::: "memory");
    for (int i = tid; i < CHB / 16; i += 512)
        cpa16(sb + OF_B + CHB + i * 16, (const char*)g_Wf + CHB + i * 16);
    asm volatile("cp.async.commit_group;" ::: "memory");

    // A fragments (held in registers for the whole pass)
    u32 ah[2][4][4], al[2][4][4];
    {
        int sub = lane >> 3;
        int rr = (lane & 7) + (sub & 1) * 8;
        int kb = (sub >> 1) * 16;
        #pragma unroll
        for (int mt = 0; mt < 2; ++mt)
            #pragma unroll
            for (int s = 0; s < 4; ++s) {
                u32 off = SWZ((warpM * 32 + mt * 16 + rr) * 128 + s * 32 + kb);
                ldmx4(ah[mt][s], sb + OF_AHI + off);
                ldmx4(al[mt][s], sb + OF_ALO + off);
            }
    }

    // ---- PASS 1: raw GEMM -> block-private L2 scratch (no c0 needed) ----
    for (int c = 0; c < 5; ++c) {
        if (c) __syncthreads();
        if (c >= 1 && c < 4) {
            const char* src = (const char*)g_Wf + (size_t)(c + 1) * CHB;
            u32 dstb = sb + OF_B + ((c + 1) & 1) * CHB;
            for (int i = tid; i < CHB / 16; i += 512)
                cpa16(dstb + i * 16, src + i * 16);
            asm volatile("cp.async.commit_group;" ::: "memory");
        }
        if (c < 4) {
            asm volatile("cp.async.wait_group 1;" ::: "memory");
        } else {
            asm volatile("cp.async.wait_group 0;" ::: "memory");
        }
        __syncthreads();

        const uint4* Bp = (const uint4*)(smb + OF_B + (c & 1) * CHB);
        #pragma unroll 1
        for (int nt = 0; nt < 6; ++nt) {
            int lt = warpN * 6 + nt;
            int tG = c * CH + lt;
            uint4 bf[4];
            #pragma unroll
            for (int s = 0; s < 4; ++s)
                bf[s] = Bp[(lt * 4 + s) * 32 + lane];

            int colb = tG * 8 + (lane & 3) * 2;

            #pragma unroll
            for (int mt = 0; mt < 2; ++mt) {
                float h0 = 0.f, h1 = 0.f, h2 = 0.f, h3 = 0.f;     // hi*hi
                float l0 = 0.f, l1 = 0.f, l2 = 0.f, l3 = 0.f;     // lo*hi
                float m0f = 0.f, m1f = 0.f, m2f = 0.f, m3f = 0.f; // hi*lo
                #pragma unroll
                for (int s = 0; s < 4; ++s) {
                    mma_bf16(h0, h1, h2, h3, ah[mt][s], bf[s].x, bf[s].y);
                    mma_bf16(l0, l1, l2, l3, al[mt][s], bf[s].x, bf[s].y);
                    mma_bf16(m0f, m1f, m2f, m3f, ah[mt][s], bf[s].z, bf[s].w);
                }
                float d0 = (h0 + l0) + m0f, d1 = (h1 + l1) + m1f;
                float d2 = (h2 + l2) + m2f, d3 = (h3 + l3) + m3f;
                int r0 = warpM * 32 + mt * 16 + (lane >> 2);
                float2 p0 = {d0, d1}, p1 = {d2, d3};
                *(float2*)&Gb[(size_t)r0 * NJ + colb] = p0;
                *(float2*)&Gb[(size_t)(r0 + 8) * NJ + colb] = p1;
            }
        }
    }
    __syncthreads();   // all G writes visible block-wide

    // wait for c0 (warm finishes well before pass 1 does), stage it
    if (tid == 0) { while (ld_acq(&g_fc0) == 0) {} }
    __syncthreads();
    for (int i = tid; i < NJ; i += 512) c0s[i] = g_c0[i];
    __syncthreads();

    // ---- PASS 2: fused c0 + relu + rowsum + normalize + store ----
    {
        int r = tid >> 2, q = tid & 3;
        const float* Gr = Gb + (size_t)r * NJ;
        float outv[16];
        float a0 = 0.f, a1 = 0.f, a2 = 0.f, a3 = 0.f;

        #pragma unroll
        for (int i = 0; i < 4; ++i) {           // cols < 64 (kept for output)
            int col = i * 16 + q * 4;
            float4 g = *(const float4*)&Gr[col];
            float4 cc = *(const float4*)&c0s[col];
            float t0 = fmaxf(g.x + cc.x, 0.f);
            float t1 = fmaxf(g.y + cc.y, 0.f);
            float t2 = fmaxf(g.z + cc.z, 0.f);
            float t3 = fmaxf(g.w + cc.w, 0.f);
            outv[i * 4 + 0] = t0; outv[i * 4 + 1] = t1;
            outv[i * 4 + 2] = t2; outv[i * 4 + 3] = t3;
            a0 += (t0 + t1) + (t2 + t3);
        }
        #pragma unroll 4
        for (int i = 4; i < 60; ++i) {
            int col = i * 16 + q * 4;
            float4 g = *(const float4*)&Gr[col];
            float4 cc = *(const float4*)&c0s[col];
            float t0 = fmaxf(g.x + cc.x, 0.f);
            float t1 = fmaxf(g.y + cc.y, 0.f);
            float t2 = fmaxf(g.z + cc.z, 0.f);
            float t3 = fmaxf(g.w + cc.w, 0.f);
            float pr = (t0 + t1) + (t2 + t3);
            switch (i & 3) {
                case 0: a0 += pr; break;
                case 1: a1 += pr; break;
                case 2: a2 += pr; break;
                default: a3 += pr; break;
            }
        }
        float s = (a0 + a1) + (a2 + a3);
        s += __shfl_xor_sync(0xffffffffu, s, 1);
        s += __shfl_xor_sync(0xffffffffu, s, 2);
        float iv = (s > 0.f) ? 1.f / s : 1.f;

        float* orow = out + (size_t)(m0 + r) * 64;
        #pragma unroll
        for (int i = 0; i < 4; ++i) {
            float4 o;
            o.x = outv[i * 4 + 0] * iv;
            o.y = outv[i * 4 + 1] * iv;
            o.z = outv[i * 4 + 2] * iv;
            o.w = outv[i * 4 + 3] * iv;
            *(float4*)&orow[i * 16 + q * 4] = o;
        }
    }
}

// -------------------- launch -------------------------------------------------
extern "C" void kernel_launch(void* const* d_in, const int* in_sizes, int n_in,
                              void* d_out, int out_size) {
    const float* inputs = (const float*)d_in[0];
    const float* ident  = (const float*)d_in[1];
    const float* enh    = (const float*)d_in[2];
    const float* inh    = (const float*)d_in[3];
    const float* beta   = (const float*)d_in[4];
    const float* delta  = (const float*)d_in[5];
    float* out = (float*)d_out;

    static int smset = 0;
    if (!smset) {
        cudaFuncSetAttribute(k_mega, cudaFuncAttributeMaxDynamicSharedMemorySize, SMB);
        smset = 1;
    }

    k_mega<<<147, 512, SMB>>>(inputs, ident, enh, inh, beta, delta, out);
}